// round 4
// baseline (speedup 1.0000x reference)
#include <cuda_runtime.h>
#include <stdint.h>

#define IN_DIM  4096
#define OUT_DIM 4096
#define BATCH   1024
#define KDIM    64
#define TOPK    64
#define NBINS   2048
#define CAND_CAP 512

// 64MB scratch for transposed weight (device global, no allocation)
__device__ float g_wt[(size_t)IN_DIM * (size_t)OUT_DIM];

// -------------------------------------------------------------------------
// Transpose W (OUT, IN) -> g_wt (IN, OUT), so gathered rows are contiguous.
// -------------------------------------------------------------------------
__global__ void transpose_kernel(const float* __restrict__ W) {
    __shared__ float tile[32][33];
    int bx = blockIdx.x * 32;   // j (columns of W)
    int by = blockIdx.y * 32;   // o (rows of W)
    int tx = threadIdx.x, ty = threadIdx.y;
    #pragma unroll
    for (int i = 0; i < 32; i += 8)
        tile[ty + i][tx] = W[(size_t)(by + ty + i) * IN_DIM + (bx + tx)];
    __syncthreads();
    #pragma unroll
    for (int i = 0; i < 32; i += 8)
        g_wt[(size_t)(bx + ty + i) * OUT_DIM + (by + tx)] = tile[tx][ty + i];
}

// -------------------------------------------------------------------------
// Fused gathered-matvec + exact top-64.
// One block per batch row b. 1024 threads, 4 outputs each (float4).
// result[b,o] = sum_k Wt[idx[b,k], o] * x[b,k] + bias[o]
// Then top-64 via histogram select + bitonic sort of candidates.
// Key = (orderable_u32(value) << 32) | ~index  -> distinct keys,
// descending sort == JAX top_k order (ties: smaller index first).
// -------------------------------------------------------------------------
__global__ __launch_bounds__(1024, 1) void router_topk_kernel(
    const float* __restrict__ x,
    const float* __restrict__ bias,
    const int*   __restrict__ prev_idx,
    float*       __restrict__ out,
    long long out_size)
{
    __shared__ float s_x[KDIM];
    __shared__ int   s_idx[KDIM];
    __shared__ unsigned long long s_keys[OUT_DIM];   // 32 KB
    __shared__ int   s_hist[NBINS];                  // 8 KB
    __shared__ unsigned long long s_cand[CAND_CAP];  // 4 KB
    __shared__ int   s_chunk[64];
    __shared__ int   s_cut;
    __shared__ int   s_cnt;

    const int b   = blockIdx.x;
    const int tid = threadIdx.x;

    if (tid < KDIM) {
        s_x[tid]   = x[b * KDIM + tid];
        s_idx[tid] = prev_idx[b * KDIM + tid];
    }
    __syncthreads();

    // ---- gathered matvec: 4 contiguous outputs per thread ----
    const int o0 = tid * 4;
    float4 acc = *reinterpret_cast<const float4*>(bias + o0);
    #pragma unroll 4
    for (int k = 0; k < KDIM; k++) {
        const int   j  = s_idx[k];
        const float xv = s_x[k];
        float4 w = *reinterpret_cast<const float4*>(g_wt + (size_t)j * OUT_DIM + o0);
        acc.x = fmaf(w.x, xv, acc.x);
        acc.y = fmaf(w.y, xv, acc.y);
        acc.z = fmaf(w.z, xv, acc.z);
        acc.w = fmaf(w.w, xv, acc.w);
    }

    // ---- build sortable keys ----
    {
        float v[4] = {acc.x, acc.y, acc.z, acc.w};
        #pragma unroll
        for (int c = 0; c < 4; c++) {
            unsigned int u = __float_as_uint(v[c]);
            u = (u & 0x80000000u) ? ~u : (u | 0x80000000u);   // orderable ascending
            s_keys[o0 + c] =
                ((unsigned long long)u << 32) | (unsigned int)(~(o0 + c));
        }
    }

    // ---- histogram on top 11 bits of mapped value ----
    s_hist[tid]        = 0;
    s_hist[tid + 1024] = 0;
    __syncthreads();
    #pragma unroll
    for (int c = 0; c < 4; c++) {
        int bin = (int)(s_keys[o0 + c] >> 53);   // u >> 21, 0..2047
        atomicAdd(&s_hist[bin], 1);
    }
    __syncthreads();

    // ---- find cutoff bin: largest bin with suffix count >= TOPK ----
    if (tid < 64) {
        int s = 0;
        #pragma unroll
        for (int i = 0; i < 32; i++) s += s_hist[tid * 32 + i];
        s_chunk[tid] = s;
    }
    __syncthreads();
    if (tid == 0) {
        int acc2 = 0;
        int ch;
        for (ch = 63; ch >= 0; ch--) {
            if (acc2 + s_chunk[ch] >= TOPK) break;
            acc2 += s_chunk[ch];
        }
        int bin;
        for (bin = ch * 32 + 31; bin >= ch * 32; bin--) {
            if (acc2 + s_hist[bin] >= TOPK) break;
            acc2 += s_hist[bin];
        }
        s_cut = bin;
        s_cnt = 0;
    }
    __syncthreads();

    // ---- extract candidates (count guaranteed >= TOPK) ----
    const int cut = s_cut;
    #pragma unroll
    for (int c = 0; c < 4; c++) {
        unsigned long long key = s_keys[o0 + c];
        if ((int)(key >> 53) >= cut) {
            int pos = atomicAdd(&s_cnt, 1);
            if (pos < CAND_CAP) s_cand[pos] = key;
        }
    }
    __syncthreads();
    const int cnt = s_cnt;

    const unsigned long long* res;
    if (cnt <= CAND_CAP) {
        // pad and bitonic-sort 512 candidates, descending
        for (int i = tid; i < CAND_CAP; i += 1024)
            if (i >= cnt) s_cand[i] = 0ULL;
        __syncthreads();
        for (int k = 2; k <= CAND_CAP; k <<= 1) {
            for (int j = k >> 1; j > 0; j >>= 1) {
                if (tid < CAND_CAP) {
                    int t = tid;
                    int ixj = t ^ j;
                    if (ixj > t) {
                        unsigned long long a = s_cand[t], bb = s_cand[ixj];
                        bool desc = ((t & k) == 0);
                        if (desc ? (a < bb) : (a > bb)) {
                            s_cand[t] = bb; s_cand[ixj] = a;
                        }
                    }
                }
                __syncthreads();
            }
        }
        res = s_cand;
    } else {
        // fallback (never expected on this data): full bitonic on 4096 keys
        for (int k = 2; k <= OUT_DIM; k <<= 1) {
            for (int j = k >> 1; j > 0; j >>= 1) {
                for (int t = tid; t < OUT_DIM; t += 1024) {
                    int ixj = t ^ j;
                    if (ixj > t) {
                        unsigned long long a = s_keys[t], bb = s_keys[ixj];
                        bool desc = ((t & k) == 0);
                        if (desc ? (a < bb) : (a > bb)) {
                            s_keys[t] = bb; s_keys[ixj] = a;
                        }
                    }
                }
                __syncthreads();
            }
        }
        res = s_keys;
    }

    // ---- emit: vals first, then indices (as float), concat order ----
    if (tid < TOPK) {
        unsigned long long key = res[tid];
        unsigned int u = (unsigned int)(key >> 32);
        unsigned int bits = (u & 0x80000000u) ? (u ^ 0x80000000u) : ~u;
        float v = __uint_as_float(bits);
        unsigned int oidx = ~(unsigned int)(key & 0xFFFFFFFFu);

        out[(size_t)b * TOPK + tid] = v;
        long long ip = (long long)BATCH * TOPK + (long long)b * TOPK + tid;
        if (ip < out_size) out[ip] = (float)oidx;
    }
}

// -------------------------------------------------------------------------
extern "C" void kernel_launch(void* const* d_in, const int* in_sizes, int n_in,
                              void* d_out, int out_size) {
    const float* x        = (const float*)d_in[0];   // (1024, 64)  f32
    const float* weight   = (const float*)d_in[1];   // (4096, 4096) f32
    const float* bias     = (const float*)d_in[2];   // (4096,) f32
    const int*   prev_idx = (const int*)d_in[3];     // (1024, 64) i32
    float* out = (float*)d_out;

    dim3 tb(32, 8);
    dim3 tg(IN_DIM / 32, OUT_DIM / 32);
    transpose_kernel<<<tg, tb>>>(weight);

    router_topk_kernel<<<BATCH, 1024>>>(x, bias, prev_idx, out, (long long)out_size);
}

// round 6
// speedup vs baseline: 1.5150x; 1.5150x over previous
#include <cuda_runtime.h>
#include <stdint.h>

#define IN_DIM  4096
#define OUT_DIM 4096
#define BATCH   1024
#define KDIM    64
#define TOPK    64
#define NBINS   2048
#define CAND_CAP 512
#define NTHREADS 512
#define OPT      8   // outputs per thread

// 64MB scratch for transposed weight (device global, no allocation)
__device__ float g_wt[(size_t)IN_DIM * (size_t)OUT_DIM];

// -------------------------------------------------------------------------
// Transpose W (OUT, IN) -> g_wt (IN, OUT), so gathered rows are contiguous.
// -------------------------------------------------------------------------
__global__ void transpose_kernel(const float* __restrict__ W) {
    __shared__ float tile[32][33];
    int bx = blockIdx.x * 32;   // j (columns of W)
    int by = blockIdx.y * 32;   // o (rows of W)
    int tx = threadIdx.x, ty = threadIdx.y;
    #pragma unroll
    for (int i = 0; i < 32; i += 8)
        tile[ty + i][tx] = W[(size_t)(by + ty + i) * IN_DIM + (bx + tx)];
    __syncthreads();
    #pragma unroll
    for (int i = 0; i < 32; i += 8)
        g_wt[(size_t)(bx + ty + i) * OUT_DIM + (by + tx)] = tile[tx][ty + i];
}

// -------------------------------------------------------------------------
// Fused gathered-matvec + exact top-64.
// One block per batch row b. 512 threads, 8 outputs each (2x float4).
// result[b,o] = sum_k Wt[idx[b,k], o] * x[b,k] + bias[o]
// Then top-64 via histogram select + bitonic sort of candidates.
// Key = (orderable_u32(value) << 32) | ~index  -> distinct keys,
// descending sort == JAX top_k order (ties: smaller index first).
// -------------------------------------------------------------------------
__global__ __launch_bounds__(NTHREADS) void router_topk_kernel(
    const float* __restrict__ x,
    const float* __restrict__ bias,
    const int*   __restrict__ prev_idx,
    float*       __restrict__ out,
    long long out_size)
{
    __shared__ float s_x[KDIM];
    __shared__ int   s_idx[KDIM];
    __shared__ unsigned long long s_keys[OUT_DIM];   // 32 KB
    __shared__ int   s_hist[NBINS];                  // 8 KB
    __shared__ unsigned long long s_cand[CAND_CAP];  // 4 KB
    __shared__ int   s_chunk[64];
    __shared__ int   s_cut;
    __shared__ int   s_cnt;

    const int b   = blockIdx.x;
    const int tid = threadIdx.x;

    if (tid < KDIM) {
        s_x[tid]   = x[b * KDIM + tid];
        s_idx[tid] = prev_idx[b * KDIM + tid];
    }
    // histogram init interleaved with load
    s_hist[tid]              = 0;
    s_hist[tid + NTHREADS]   = 0;
    s_hist[tid + 2*NTHREADS] = 0;
    s_hist[tid + 3*NTHREADS] = 0;
    __syncthreads();

    // ---- gathered matvec: 8 contiguous outputs per thread ----
    const int o0 = tid * OPT;
    float4 a0 = *reinterpret_cast<const float4*>(bias + o0);
    float4 a1 = *reinterpret_cast<const float4*>(bias + o0 + 4);

    #pragma unroll 4
    for (int k = 0; k < KDIM; k++) {
        const int   j  = s_idx[k];
        const float xv = s_x[k];
        const float4* p = reinterpret_cast<const float4*>(
            g_wt + (size_t)j * OUT_DIM + o0);
        float4 w0 = p[0];
        float4 w1 = p[1];
        a0.x = fmaf(w0.x, xv, a0.x);
        a0.y = fmaf(w0.y, xv, a0.y);
        a0.z = fmaf(w0.z, xv, a0.z);
        a0.w = fmaf(w0.w, xv, a0.w);
        a1.x = fmaf(w1.x, xv, a1.x);
        a1.y = fmaf(w1.y, xv, a1.y);
        a1.z = fmaf(w1.z, xv, a1.z);
        a1.w = fmaf(w1.w, xv, a1.w);
    }

    // ---- build sortable keys + histogram on top 11 bits ----
    {
        float v[OPT] = {a0.x, a0.y, a0.z, a0.w, a1.x, a1.y, a1.z, a1.w};
        #pragma unroll
        for (int c = 0; c < OPT; c++) {
            unsigned int u = __float_as_uint(v[c]);
            u = (u & 0x80000000u) ? ~u : (u | 0x80000000u);   // orderable ascending
            unsigned long long key =
                ((unsigned long long)u << 32) | (unsigned int)(~(o0 + c));
            s_keys[o0 + c] = key;
        }
    }
    __syncthreads();   // ensure hist zeroed before atomics (done above pre-loop)

    #pragma unroll
    for (int c = 0; c < OPT; c++) {
        int bin = (int)(s_keys[o0 + c] >> 53);   // u >> 21, 0..2047
        atomicAdd(&s_hist[bin], 1);
    }
    __syncthreads();

    // ---- find cutoff bin: largest bin with suffix count >= TOPK ----
    if (tid < 64) {
        int s = 0;
        #pragma unroll
        for (int i = 0; i < 32; i++) s += s_hist[tid * 32 + i];
        s_chunk[tid] = s;
    }
    __syncthreads();
    if (tid == 0) {
        int acc2 = 0;
        int ch;
        for (ch = 63; ch >= 0; ch--) {
            if (acc2 + s_chunk[ch] >= TOPK) break;
            acc2 += s_chunk[ch];
        }
        int bin;
        for (bin = ch * 32 + 31; bin >= ch * 32; bin--) {
            if (acc2 + s_hist[bin] >= TOPK) break;
            acc2 += s_hist[bin];
        }
        s_cut = bin;
        s_cnt = 0;
    }
    __syncthreads();

    // ---- extract candidates (count guaranteed >= TOPK) ----
    const int cut = s_cut;
    #pragma unroll
    for (int c = 0; c < OPT; c++) {
        unsigned long long key = s_keys[o0 + c];
        if ((int)(key >> 53) >= cut) {
            int pos = atomicAdd(&s_cnt, 1);
            if (pos < CAND_CAP) s_cand[pos] = key;
        }
    }
    __syncthreads();
    const int cnt = s_cnt;

    const unsigned long long* res;
    if (cnt <= CAND_CAP) {
        // pad and bitonic-sort 512 candidates, descending (1 elem/thread)
        if (tid >= cnt) s_cand[tid] = 0ULL;
        __syncthreads();
        #pragma unroll
        for (int k = 2; k <= CAND_CAP; k <<= 1) {
            for (int j = k >> 1; j > 0; j >>= 1) {
                int t = tid;
                int ixj = t ^ j;
                if (ixj > t) {
                    unsigned long long a = s_cand[t], bb = s_cand[ixj];
                    bool desc = ((t & k) == 0);
                    if (desc ? (a < bb) : (a > bb)) {
                        s_cand[t] = bb; s_cand[ixj] = a;
                    }
                }
                __syncthreads();
            }
        }
        res = s_cand;
    } else {
        // fallback (never expected on this data): full bitonic on 4096 keys
        for (int k = 2; k <= OUT_DIM; k <<= 1) {
            for (int j = k >> 1; j > 0; j >>= 1) {
                for (int t = tid; t < OUT_DIM; t += NTHREADS) {
                    int ixj = t ^ j;
                    if (ixj > t) {
                        unsigned long long a = s_keys[t], bb = s_keys[ixj];
                        bool desc = ((t & k) == 0);
                        if (desc ? (a < bb) : (a > bb)) {
                            s_keys[t] = bb; s_keys[ixj] = a;
                        }
                    }
                }
                __syncthreads();
            }
        }
        res = s_keys;
    }

    // ---- emit: vals first, then indices (as float), concat order ----
    if (tid < TOPK) {
        unsigned long long key = res[tid];
        unsigned int u = (unsigned int)(key >> 32);
        unsigned int bits = (u & 0x80000000u) ? (u ^ 0x80000000u) : ~u;
        float v = __uint_as_float(bits);
        unsigned int oidx = ~(unsigned int)(key & 0xFFFFFFFFu);

        out[(size_t)b * TOPK + tid] = v;
        long long ip = (long long)BATCH * TOPK + (long long)b * TOPK + tid;
        if (ip < out_size) out[ip] = (float)oidx;
    }
}

// -------------------------------------------------------------------------
extern "C" void kernel_launch(void* const* d_in, const int* in_sizes, int n_in,
                              void* d_out, int out_size) {
    const float* x        = (const float*)d_in[0];   // (1024, 64)  f32
    const float* weight   = (const float*)d_in[1];   // (4096, 4096) f32
    const float* bias     = (const float*)d_in[2];   // (4096,) f32
    const int*   prev_idx = (const int*)d_in[3];     // (1024, 64) i32
    float* out = (float*)d_out;

    dim3 tb(32, 8);
    dim3 tg(IN_DIM / 32, OUT_DIM / 32);
    transpose_kernel<<<tg, tb>>>(weight);

    router_topk_kernel<<<BATCH, NTHREADS>>>(x, bias, prev_idx, out,
                                            (long long)out_size);
}